// round 4
// baseline (speedup 1.0000x reference)
#include <cuda_runtime.h>
#include <math.h>

// Problem constants (from reference)
#define C_VOL0     0.2f
#define C_DIFF     (0.3f*0.3f + 0.2f*0.2f)   // 0.13
#define C_FEEDBACK 1.0f
#define C_INTENS   1.0f
#define C_MEANREV  0.1f

#define NTHREADS 1024

// Per-batch scalar partials (deterministic finalize)
__device__ float g_cost[512];
__device__ float g_term[512];

// ---------------------------------------------------------------------------
// Main persistent kernel: one block per batch, density kept in SMEM across all
// time steps. Tridiagonal solve via PCR in shared memory.
// ---------------------------------------------------------------------------
__global__ void __launch_bounds__(NTHREADS, 1)
fp_main(const float* __restrict__ mesh_time,
        const float* __restrict__ mesh_space,
        const float* __restrict__ init,
        const float* __restrict__ bw,
        float* __restrict__ out_density,
        int T, int N, int B)
{
    extern __shared__ float sm[];
    const int b   = blockIdx.x;
    const int tid = threadIdx.x;

    // shared layout: 16 * N floats
    float* xi   = sm;            // x interior
    float* wA   = xi  + N;       // trapezoid weights
    float* fs   = wA  + N;       // 1/(2 dx_f)
    float* bs   = fs  + N;       // 1/(2 dx_b)
    float* uf   = bs  + N;       // 1/(ctl*dx_f)
    float* ub   = uf  + N;       // 1/(ctl*dx_b)
    float* dens = ub  + N;
    float* tmp  = dens + N;      // first-derivative scratch
    float* A0 = tmp + N;  float* B0 = A0 + N;  float* C0 = B0 + N;  float* D0 = C0 + N;
    float* A1 = D0 + N;   float* B1 = A1 + N;  float* C1 = B1 + N;  float* D1 = C1 + N;

    __shared__ float red[96];
    __shared__ float bcast[4];

    // ---- setup: geometry from actual mesh floats + initial condition ----
    for (int i = tid; i < N; i += NTHREADS) {
        float xm = mesh_space[i];
        float xc = mesh_space[i + 1];
        float xp = mesh_space[i + 2];
        xi[i] = xc;
        wA[i] = (xp - xm) * 0.5f;
        float dxf = xp - xc;
        float dxb = xc - xm;
        fs[i] = 1.0f / (2.0f * dxf);
        bs[i] = 1.0f / (2.0f * dxb);
        float ctl = xp - xm;
        uf[i] = 1.0f / (ctl * dxf);
        ub[i] = 1.0f / (ctl * dxb);
        float d0 = init[i];
        dens[i] = d0;
        out_density[(size_t)b * T * N + i] = d0;   // t = 0 slice
    }
    __syncthreads();

    const int lane = tid & 31;
    const int warp = tid >> 5;
    const int NW   = NTHREADS >> 5;
    float costacc = 0.0f;   // meaningful on tid==0 only

    for (int t = 0; t < T - 1; ++t) {
        const float dt = mesh_time[t + 1] - mesh_time[t];
        const float dW = bw[(size_t)b * (T - 1) + t];

        // ---- fused reductions: mean, feedback, control cost ----
        float s_mean = 0.f, s_fb = 0.f, s_cost = 0.f;
        for (int i = tid; i < N; i += NTHREADS) {
            float dwv = dens[i] * wA[i];
            float x   = xi[i];
            s_mean += x * dwv;
            s_fb   += fmaxf(-x, 0.0f) * dwv;
            s_cost += 0.125f * x * x * dwv;     // (0.5 x)^2 / 2
        }
        #pragma unroll
        for (int o = 16; o > 0; o >>= 1) {
            s_mean += __shfl_down_sync(0xffffffffu, s_mean, o);
            s_fb   += __shfl_down_sync(0xffffffffu, s_fb,   o);
            s_cost += __shfl_down_sync(0xffffffffu, s_cost, o);
        }
        if (lane == 0) { red[warp] = s_mean; red[32 + warp] = s_fb; red[64 + warp] = s_cost; }
        __syncthreads();
        if (warp == 0) {
            float a = (lane < NW) ? red[lane]      : 0.0f;
            float f = (lane < NW) ? red[32 + lane] : 0.0f;
            float c = (lane < NW) ? red[64 + lane] : 0.0f;
            #pragma unroll
            for (int o = 16; o > 0; o >>= 1) {
                a += __shfl_down_sync(0xffffffffu, a, o);
                f += __shfl_down_sync(0xffffffffu, f, o);
                c += __shfl_down_sync(0xffffffffu, c, o);
            }
            if (lane == 0) { bcast[0] = a; bcast[1] = f; bcast[2] = c; }
        }
        __syncthreads();
        const float mean = bcast[0];
        const float fb   = C_FEEDBACK * bcast[1];
        if (tid == 0) costacc += dt * bcast[2];

        // ---- first derivative stencil (zero-padded density) ----
        for (int i = tid; i < N; i += NTHREADS) {
            float dm = (i > 0)     ? dens[i - 1] : 0.0f;
            float dc = dens[i];
            float dp = (i < N - 1) ? dens[i + 1] : 0.0f;
            tmp[i] = fs[i] * (dp - dc) + bs[i] * (dc - dm);
        }
        __syncthreads();

        // ---- fused: stochastic RHS + tridiagonal build ----
        // coeff(x) = -0.5 x + fb - MEANREV*(mean - x)  (pure pointwise in xi)
        const float delta_t = C_VOL0 * C_VOL0 * (dW * dW - dt) * 0.5f;
        const float vdW = C_VOL0 * dW;
        const float Ddt = C_DIFF * dt;
        for (int i = tid; i < N; i += NTHREADS) {
            // stochastic RHS
            float gm = (i > 0)     ? tmp[i - 1] : 0.0f;
            float gc = tmp[i];
            float gp = (i < N - 1) ? tmp[i + 1] : 0.0f;
            float diff2 = delta_t * (fs[i] * (gp - gc) + bs[i] * (gc - gm));
            D0[i] = dens[i] - (vdW * gc - diff2);

            // tridiagonal coefficients
            float x  = xi[i];
            float cc = -0.5f * x + fb - C_MEANREV * (mean - x);
            float fc = dt * fs[i];
            float bc = dt * bs[i];
            float supv = 0.0f, subv = 0.0f;
            if (i < N - 1) {
                float xp1 = xi[i + 1];
                float cp1 = -0.5f * xp1 + fb - C_MEANREV * (mean - xp1);
                supv = -fc * cp1 - Ddt * uf[i];
            }
            if (i > 0) {
                float xm1 = xi[i - 1];
                float cm1 = -0.5f * xm1 + fb - C_MEANREV * (mean - xm1);
                subv = bc * cm1 - Ddt * ub[i];
            }
            float mainv = 1.0f + dt * C_INTENS * fmaxf(-x, 0.0f)
                        - (bc - fc) * cc
                        + Ddt * (uf[i] + ub[i]);
            A0[i] = subv;  B0[i] = mainv;  C0[i] = supv;
        }
        __syncthreads();

        // ---- PCR solve (11 levels for N=2048) ----
        float *Aa = A0, *Bb = B0, *Cc = C0, *Dd = D0;
        float *Aw = A1, *Bw = B1, *Cw = C1, *Dw = D1;
        for (int s = 1; s < N; s <<= 1) {
            for (int i = tid; i < N; i += NTHREADS) {
                int im = i - s, ip = i + s;
                float aim, cim, dim, bim;
                if (im >= 0) { aim = Aa[im]; bim = Bb[im]; cim = Cc[im]; dim = Dd[im]; }
                else         { aim = 0.f; bim = 1.f; cim = 0.f; dim = 0.f; }
                float aip, cip, dip, bip;
                if (ip < N)  { aip = Aa[ip]; bip = Bb[ip]; cip = Cc[ip]; dip = Dd[ip]; }
                else         { aip = 0.f; bip = 1.f; cip = 0.f; dip = 0.f; }
                float al = -Aa[i] * __frcp_rn(bim);
                float be = -Cc[i] * __frcp_rn(bip);
                Aw[i] = al * aim;
                Cw[i] = be * cip;
                Bw[i] = Bb[i] + al * cim + be * aip;
                Dw[i] = Dd[i] + al * dim + be * dip;
            }
            __syncthreads();
            float* tp;
            tp = Aa; Aa = Aw; Aw = tp;
            tp = Bb; Bb = Bw; Bw = tp;
            tp = Cc; Cc = Cw; Cw = tp;
            tp = Dd; Dd = Dw; Dw = tp;
        }

        // ---- extract solution, update density, stream trajectory out ----
        const size_t ob = (size_t)b * T * N + (size_t)(t + 1) * N;
        for (int i = tid; i < N; i += NTHREADS) {
            float x = Dd[i] / Bb[i];
            dens[i] = x;
            out_density[ob + i] = x;
        }
        __syncthreads();
    }

    // ---- terminal second moment + cost partials ----
    float s_t = 0.f;
    for (int i = tid; i < N; i += NTHREADS) {
        float x = xi[i];
        s_t += x * x * dens[i] * wA[i];
    }
    #pragma unroll
    for (int o = 16; o > 0; o >>= 1) s_t += __shfl_down_sync(0xffffffffu, s_t, o);
    if (lane == 0) red[warp] = s_t;
    __syncthreads();
    if (warp == 0) {
        float a = (lane < NW) ? red[lane] : 0.0f;
        #pragma unroll
        for (int o = 16; o > 0; o >>= 1) a += __shfl_down_sync(0xffffffffu, a, o);
        if (lane == 0) g_term[b] = a;
    }
    if (tid == 0) g_cost[b] = costacc;
}

// ---------------------------------------------------------------------------
// Deterministic finalize: average per-batch partials into the 2 cost slots.
// ---------------------------------------------------------------------------
__global__ void fp_finalize(float* __restrict__ out, int B, size_t off)
{
    __shared__ float rc[32], rt[32];
    int tid = threadIdx.x;
    float c = 0.0f, t = 0.0f;
    for (int i = tid; i < B; i += blockDim.x) { c += g_cost[i]; t += g_term[i]; }
    #pragma unroll
    for (int o = 16; o > 0; o >>= 1) {
        c += __shfl_down_sync(0xffffffffu, c, o);
        t += __shfl_down_sync(0xffffffffu, t, o);
    }
    int lane = tid & 31, warp = tid >> 5;
    if (lane == 0) { rc[warp] = c; rt[warp] = t; }
    __syncthreads();
    if (tid == 0) {
        float cs = 0.f, ts = 0.f;
        int nw = (blockDim.x + 31) >> 5;
        for (int wgt = 0; wgt < nw; ++wgt) { cs += rc[wgt]; ts += rt[wgt]; }
        out[off]     = cs / (float)B;   // sum_t dt * mean_B(integral)
        out[off + 1] = ts / (float)B;   // mean_B(terminal second moment)
    }
}

extern "C" void kernel_launch(void* const* d_in, const int* in_sizes, int n_in,
                              void* d_out, int out_size)
{
    const float* mesh_time  = (const float*)d_in[0];
    const float* mesh_space = (const float*)d_in[1];
    const float* init       = (const float*)d_in[2];
    const float* bw         = (const float*)d_in[3];
    float* out = (float*)d_out;

    int T  = in_sizes[0];           // 129
    int Nx = in_sizes[1];           // 2050
    int N  = Nx - 2;                // 2048
    int B  = in_sizes[3] / (T - 1); // 128

    size_t smem = (size_t)16 * N * sizeof(float);   // 131072 B
    cudaFuncSetAttribute(fp_main, cudaFuncAttributeMaxDynamicSharedMemorySize, (int)smem);

    fp_main<<<B, NTHREADS, smem>>>(mesh_time, mesh_space, init, bw, out, T, N, B);
    fp_finalize<<<1, 128>>>(out, B, (size_t)B * T * N);
}

// round 6
// speedup vs baseline: 3.2461x; 3.2461x over previous
#include <cuda_runtime.h>
#include <math.h>

// Problem constants (from reference)
#define C_VOL0     0.2f
#define C_DIFF     (0.3f*0.3f + 0.2f*0.2f)   // 0.13
#define C_MEANREV  0.1f

#define P  256          // threads per block
#define M  8            // rows per thread (N = P*M = 2048)
#define NW (P/32)       // warps per block

// Per-batch scalar partials (deterministic finalize)
__device__ float g_cost[512];
__device__ float g_term[512];

// ---------------------------------------------------------------------------
// One block per batch. Density + geometry in SMEM for all time steps.
// Tridiagonal solve: per-thread register Thomas on 8-row chunks + PCR on the
// 256-unknown reduced interface system.
// ---------------------------------------------------------------------------
__global__ void __launch_bounds__(P, 1)
fp_main(const float* __restrict__ mesh_time,
        const float* __restrict__ mesh_space,
        const float* __restrict__ init,
        const float* __restrict__ bw,
        float* __restrict__ out_density,
        int T, int N, int B)
{
    extern __shared__ float sm[];
    const int b   = blockIdx.x;
    const int tid = threadIdx.x;
    const int lane = tid & 31;
    const int warp = tid >> 5;
    const int s0   = tid * M;          // first global row owned by this thread

    // shared layout
    float* xi   = sm;            // x interior                      [N]
    float* wA   = xi  + N;       // trapezoid weights               [N]
    float* fs   = wA  + N;       // 1/(2 dx_f)                      [N]
    float* bs   = fs  + N;       // 1/(2 dx_b)                      [N]
    float* uf   = bs  + N;       // 1/(ctl*dx_f)                    [N]
    float* ub   = uf  + N;       // 1/(ctl*dx_b)                    [N]
    float* dens = ub  + N;       //                                 [N]
    float* tmp  = dens + N;      // first-derivative scratch        [N]
    float* RA0  = tmp + N;       // reduced system (double buffer)  [8*P]
    float* RB0 = RA0 + P;  float* RC0 = RB0 + P;  float* RD0 = RC0 + P;
    float* RA1 = RD0 + P;  float* RB1 = RA1 + P;  float* RC1 = RB1 + P;  float* RD1 = RC1 + P;
    float* ephi = RD1 + P;            // [P+1] interface exchange
    float* ealp = ephi + (P + 1);     // [P+1]
    float* egam = ealp + (P + 1);     // [P+1]
    float* sol  = egam + (P + 1);     // [P]

    __shared__ float red[3 * NW];
    __shared__ float bcast[3];

    // ---- setup: geometry from actual mesh floats + initial condition ----
    for (int i = tid; i < N; i += P) {
        float xm = mesh_space[i];
        float xc = mesh_space[i + 1];
        float xp = mesh_space[i + 2];
        xi[i] = xc;
        wA[i] = (xp - xm) * 0.5f;
        float dxf = xp - xc;
        float dxb = xc - xm;
        fs[i] = 1.0f / (2.0f * dxf);
        bs[i] = 1.0f / (2.0f * dxb);
        float ctl = xp - xm;
        uf[i] = 1.0f / (ctl * dxf);
        ub[i] = 1.0f / (ctl * dxb);
        float d0 = init[i];
        dens[i] = d0;
        out_density[(size_t)b * T * N + i] = d0;   // t = 0 slice
    }
    if (tid == 0) { ephi[P] = 0.f; ealp[P] = 0.f; egam[P] = 0.f; }
    __syncthreads();

    // ---- initial reductions for density0 ----
    {
        float s_mean = 0.f, s_fb = 0.f, s_cost = 0.f;
        for (int i = tid; i < N; i += P) {
            float dwv = dens[i] * wA[i];
            float x   = xi[i];
            s_mean += x * dwv;
            s_fb   += fmaxf(-x, 0.0f) * dwv;
            s_cost += 0.125f * x * x * dwv;
        }
        #pragma unroll
        for (int o = 16; o > 0; o >>= 1) {
            s_mean += __shfl_down_sync(0xffffffffu, s_mean, o);
            s_fb   += __shfl_down_sync(0xffffffffu, s_fb,   o);
            s_cost += __shfl_down_sync(0xffffffffu, s_cost, o);
        }
        if (lane == 0) { red[warp] = s_mean; red[NW + warp] = s_fb; red[2 * NW + warp] = s_cost; }
    }
    __syncthreads();

    float costacc = 0.0f;   // meaningful on tid==0 only

    for (int st = 0; st < T - 1; ++st) {
        const float dt = mesh_time[st + 1] - mesh_time[st];
        const float dW = bw[(size_t)b * (T - 1) + st];

        // ---- finalize block reduction of previous density ----
        if (warp == 0) {
            float a = (lane < NW) ? red[lane]          : 0.0f;
            float f = (lane < NW) ? red[NW + lane]     : 0.0f;
            float c = (lane < NW) ? red[2 * NW + lane] : 0.0f;
            #pragma unroll
            for (int o = 4; o > 0; o >>= 1) {
                a += __shfl_down_sync(0xffffffffu, a, o);
                f += __shfl_down_sync(0xffffffffu, f, o);
                c += __shfl_down_sync(0xffffffffu, c, o);
            }
            if (lane == 0) { bcast[0] = a; bcast[1] = f; bcast[2] = c; }
        }
        __syncthreads();
        const float mean = bcast[0];
        const float fb   = bcast[1];           // FEEDBACK = 1
        if (tid == 0) costacc += dt * bcast[2];

        // ---- first derivative stencil (zero-padded density) ----
        for (int i = tid; i < N; i += P) {
            float dm = (i > 0)     ? dens[i - 1] : 0.0f;
            float dc = dens[i];
            float dp = (i < N - 1) ? dens[i + 1] : 0.0f;
            tmp[i] = fs[i] * (dp - dc) + bs[i] * (dc - dm);
        }
        __syncthreads();

        // ---- per-thread coefficient build (registers, float4 slice loads) ----
        const float delta_t = C_VOL0 * C_VOL0 * (dW * dW - dt) * 0.5f;
        const float vdW = C_VOL0 * dW;
        const float Ddt = C_DIFF * dt;
        const float K1  = fb - C_MEANREV * mean;       // coeff(x) = K1 + Kx*x
        const float Kx  = C_MEANREV - 0.5f;

        float xiv[M], fsv[M], bsv[M], ufv[M], ubv[M], dnv[M], tpv[M];
        {
            const float4* p4;
            p4 = (const float4*)(xi  + s0); { float4 v0 = p4[0], v1 = p4[1];
                xiv[0]=v0.x; xiv[1]=v0.y; xiv[2]=v0.z; xiv[3]=v0.w; xiv[4]=v1.x; xiv[5]=v1.y; xiv[6]=v1.z; xiv[7]=v1.w; }
            p4 = (const float4*)(fs  + s0); { float4 v0 = p4[0], v1 = p4[1];
                fsv[0]=v0.x; fsv[1]=v0.y; fsv[2]=v0.z; fsv[3]=v0.w; fsv[4]=v1.x; fsv[5]=v1.y; fsv[6]=v1.z; fsv[7]=v1.w; }
            p4 = (const float4*)(bs  + s0); { float4 v0 = p4[0], v1 = p4[1];
                bsv[0]=v0.x; bsv[1]=v0.y; bsv[2]=v0.z; bsv[3]=v0.w; bsv[4]=v1.x; bsv[5]=v1.y; bsv[6]=v1.z; bsv[7]=v1.w; }
            p4 = (const float4*)(uf  + s0); { float4 v0 = p4[0], v1 = p4[1];
                ufv[0]=v0.x; ufv[1]=v0.y; ufv[2]=v0.z; ufv[3]=v0.w; ufv[4]=v1.x; ufv[5]=v1.y; ufv[6]=v1.z; ufv[7]=v1.w; }
            p4 = (const float4*)(ub  + s0); { float4 v0 = p4[0], v1 = p4[1];
                ubv[0]=v0.x; ubv[1]=v0.y; ubv[2]=v0.z; ubv[3]=v0.w; ubv[4]=v1.x; ubv[5]=v1.y; ubv[6]=v1.z; ubv[7]=v1.w; }
            p4 = (const float4*)(dens+ s0); { float4 v0 = p4[0], v1 = p4[1];
                dnv[0]=v0.x; dnv[1]=v0.y; dnv[2]=v0.z; dnv[3]=v0.w; dnv[4]=v1.x; dnv[5]=v1.y; dnv[6]=v1.z; dnv[7]=v1.w; }
            p4 = (const float4*)(tmp + s0); { float4 v0 = p4[0], v1 = p4[1];
                tpv[0]=v0.x; tpv[1]=v0.y; tpv[2]=v0.z; tpv[3]=v0.w; tpv[4]=v1.x; tpv[5]=v1.y; tpv[6]=v1.z; tpv[7]=v1.w; }
        }
        const float tm_m = (tid > 0)     ? tmp[s0 - 1] : 0.0f;
        const float tm_p = (tid < P - 1) ? tmp[s0 + M] : 0.0f;
        const float xi_m = (tid > 0)     ? xi[s0 - 1]  : 0.0f;
        const float xi_p = (tid < P - 1) ? xi[s0 + M]  : 0.0f;

        float av[M], bvv[M], cv[M], dv[M];
        #pragma unroll
        for (int j = 0; j < M; ++j) {
            const int i = s0 + j;
            // stochastic RHS
            float gm = (j > 0)     ? tpv[j - 1] : tm_m;
            float gc = tpv[j];
            float gp = (j < M - 1) ? tpv[j + 1] : tm_p;
            float diff2 = delta_t * (fsv[j] * (gp - gc) + bsv[j] * (gc - gm));
            dv[j] = dnv[j] - (vdW * gc - diff2);
            // tridiagonal coefficients
            float x  = xiv[j];
            float fc = dt * fsv[j];
            float bc = dt * bsv[j];
            float xp = (j < M - 1) ? xiv[j + 1] : xi_p;
            float xm = (j > 0)     ? xiv[j - 1] : xi_m;
            cv[j]  = (i < N - 1) ? (-fc * (K1 + Kx * xp) - Ddt * ufv[j]) : 0.0f;
            av[j]  = (i > 0)     ? ( bc * (K1 + Kx * xm) - Ddt * ubv[j]) : 0.0f;
            bvv[j] = 1.0f + dt * fmaxf(-x, 0.0f)
                   - (bc - fc) * (K1 + Kx * x)
                   + Ddt * (ufv[j] + ubv[j]);
        }

        // ---- local elimination of M-1 interior rows (registers) ----
        // forward: x_j = Dw - Aw*X_{t-1} - Cw*x_{j+1}
        float Dw[M - 1], Aw[M - 1], Cw[M - 1];
        {
            float r = __frcp_rn(bvv[0]);
            Dw[0] = r * dv[0];  Aw[0] = r * av[0];  Cw[0] = r * cv[0];
        }
        #pragma unroll
        for (int j = 1; j < M - 1; ++j) {
            float r = __frcp_rn(bvv[j] - av[j] * Cw[j - 1]);
            Dw[j] = r * (dv[j] - av[j] * Dw[j - 1]);
            Aw[j] = -r * av[j] * Aw[j - 1];
            Cw[j] = r * cv[j];
        }
        // backward: x_j = Dw - Aw*X_{t-1} - Cw*X_t   (X_t = chunk-last unknown)
        #pragma unroll
        for (int j = M - 3; j >= 0; --j) {
            Dw[j] = Dw[j] - Cw[j] * Dw[j + 1];
            Aw[j] = Aw[j] - Cw[j] * Aw[j + 1];
            Cw[j] = -Cw[j] * Cw[j + 1];
        }

        // exchange first-interior-row representation with neighbor thread
        ephi[tid] = Dw[0];  ealp[tid] = Aw[0];  egam[tid] = Cw[0];
        __syncthreads();

        // ---- reduced interface equation (row s0+M-1) ----
        {
            float ae = av[M - 1], be = bvv[M - 1], ce = cv[M - 1], de = dv[M - 1];
            float pn = ephi[tid + 1], an = ealp[tid + 1], gn = egam[tid + 1];
            RA0[tid] = -ae * Aw[M - 2];
            RB0[tid] =  be - ae * Cw[M - 2] - ce * an;
            RC0[tid] = -ce * gn;
            RD0[tid] =  de - ae * Dw[M - 2] - ce * pn;
        }
        __syncthreads();

        // ---- PCR on reduced system (P rows, 1 per thread, 8 levels) ----
        float *Aa = RA0, *Bb = RB0, *Cc = RC0, *Dd = RD0;
        float *Ax = RA1, *Bx = RB1, *Cx = RC1, *Dx = RD1;
        for (int sh = 1; sh < P; sh <<= 1) {
            int im = tid - sh, ip = tid + sh;
            float aim, bim, cim, dim;
            if (im >= 0) { aim = Aa[im]; bim = Bb[im]; cim = Cc[im]; dim = Dd[im]; }
            else         { aim = 0.f; bim = 1.f; cim = 0.f; dim = 0.f; }
            float aip, bip, cip, dip;
            if (ip < P)  { aip = Aa[ip]; bip = Bb[ip]; cip = Cc[ip]; dip = Dd[ip]; }
            else         { aip = 0.f; bip = 1.f; cip = 0.f; dip = 0.f; }
            float al = -Aa[tid] * __frcp_rn(bim);
            float be = -Cc[tid] * __frcp_rn(bip);
            float na = al * aim;
            float nc = be * cip;
            float nb = Bb[tid] + al * cim + be * aip;
            float nd = Dd[tid] + al * dim + be * dip;
            __syncthreads();
            Ax[tid] = na; Bx[tid] = nb; Cx[tid] = nc; Dx[tid] = nd;
            __syncthreads();
            float* tp;
            tp = Aa; Aa = Ax; Ax = tp;
            tp = Bb; Bb = Bx; Bx = tp;
            tp = Cc; Cc = Cx; Cx = tp;
            tp = Dd; Dd = Dx; Dx = tp;
        }
        float Xt = Dd[tid] / Bb[tid];
        sol[tid] = Xt;
        __syncthreads();
        float Xm = (tid > 0) ? sol[tid - 1] : 0.0f;

        // ---- back-substitution, density update, trajectory out, reductions ----
        float xv[M];
        #pragma unroll
        for (int j = 0; j < M - 1; ++j)
            xv[j] = Dw[j] - Aw[j] * Xm - Cw[j] * Xt;
        xv[M - 1] = Xt;

        {
            float4* q4 = (float4*)(dens + s0);
            float4 v0, v1;
            v0.x = xv[0]; v0.y = xv[1]; v0.z = xv[2]; v0.w = xv[3];
            v1.x = xv[4]; v1.y = xv[5]; v1.z = xv[6]; v1.w = xv[7];
            q4[0] = v0; q4[1] = v1;
            float4* g4 = (float4*)(out_density + (size_t)b * T * N + (size_t)(st + 1) * N + s0);
            g4[0] = v0; g4[1] = v1;
        }

        // fused reductions for the new density (feeds next step)
        {
            const float4* p4 = (const float4*)(wA + s0);
            float4 w0 = p4[0], w1 = p4[1];
            float wv[M] = {w0.x, w0.y, w0.z, w0.w, w1.x, w1.y, w1.z, w1.w};
            float s_mean = 0.f, s_fb = 0.f, s_cost = 0.f;
            #pragma unroll
            for (int j = 0; j < M; ++j) {
                float dwv = xv[j] * wv[j];
                float x   = xiv[j];
                s_mean += x * dwv;
                s_fb   += fmaxf(-x, 0.0f) * dwv;
                s_cost += 0.125f * x * x * dwv;
            }
            #pragma unroll
            for (int o = 16; o > 0; o >>= 1) {
                s_mean += __shfl_down_sync(0xffffffffu, s_mean, o);
                s_fb   += __shfl_down_sync(0xffffffffu, s_fb,   o);
                s_cost += __shfl_down_sync(0xffffffffu, s_cost, o);
            }
            if (lane == 0) { red[warp] = s_mean; red[NW + warp] = s_fb; red[2 * NW + warp] = s_cost; }
        }
        __syncthreads();
    }

    // ---- terminal second moment + cost partials ----
    float s_t = 0.f;
    for (int i = tid; i < N; i += P) {
        float x = xi[i];
        s_t += x * x * dens[i] * wA[i];
    }
    #pragma unroll
    for (int o = 16; o > 0; o >>= 1) s_t += __shfl_down_sync(0xffffffffu, s_t, o);
    if (lane == 0) red[warp] = s_t;
    __syncthreads();
    if (warp == 0) {
        float a = (lane < NW) ? red[lane] : 0.0f;
        #pragma unroll
        for (int o = 4; o > 0; o >>= 1) a += __shfl_down_sync(0xffffffffu, a, o);
        if (lane == 0) g_term[b] = a;
    }
    if (tid == 0) g_cost[b] = costacc;
}

// ---------------------------------------------------------------------------
// Deterministic finalize: average per-batch partials into the 2 cost slots.
// ---------------------------------------------------------------------------
__global__ void fp_finalize(float* __restrict__ out, int B, size_t off)
{
    __shared__ float rc[32], rt[32];
    int tid = threadIdx.x;
    float c = 0.0f, t = 0.0f;
    for (int i = tid; i < B; i += blockDim.x) { c += g_cost[i]; t += g_term[i]; }
    #pragma unroll
    for (int o = 16; o > 0; o >>= 1) {
        c += __shfl_down_sync(0xffffffffu, c, o);
        t += __shfl_down_sync(0xffffffffu, t, o);
    }
    int lane = tid & 31, warp = tid >> 5;
    if (lane == 0) { rc[warp] = c; rt[warp] = t; }
    __syncthreads();
    if (tid == 0) {
        float cs = 0.f, ts = 0.f;
        int nw = (blockDim.x + 31) >> 5;
        for (int wgt = 0; wgt < nw; ++wgt) { cs += rc[wgt]; ts += rt[wgt]; }
        out[off]     = cs / (float)B;
        out[off + 1] = ts / (float)B;
    }
}

extern "C" void kernel_launch(void* const* d_in, const int* in_sizes, int n_in,
                              void* d_out, int out_size)
{
    const float* mesh_time  = (const float*)d_in[0];
    const float* mesh_space = (const float*)d_in[1];
    const float* init       = (const float*)d_in[2];
    const float* bw         = (const float*)d_in[3];
    float* out = (float*)d_out;

    int T  = in_sizes[0];           // 129
    int Nx = in_sizes[1];           // 2050
    int N  = Nx - 2;                // 2048 (= P*M)
    int B  = in_sizes[3] / (T - 1); // 128

    size_t smem = ((size_t)8 * N + 8 * P + 3 * (P + 1) + P) * sizeof(float); // ~77.9 KB
    cudaFuncSetAttribute(fp_main, cudaFuncAttributeMaxDynamicSharedMemorySize, (int)smem);

    fp_main<<<B, P, smem>>>(mesh_time, mesh_space, init, bw, out, T, N, B);
    fp_finalize<<<1, 128>>>(out, B, (size_t)B * T * N);
}

// round 8
// speedup vs baseline: 4.9296x; 1.5186x over previous
#include <cuda_runtime.h>
#include <math.h>

// Problem constants (from reference)
#define C_VOL0     0.2f
#define C_DIFF     0.13f              // VOL^2 + VOL0^2
#define C_MEANREV  0.1f

#define P  256          // threads per block
#define M  8            // rows per thread (N = P*M = 2048)
#define NW (P/32)       // warps per block

// Per-batch scalar partials (deterministic finalize)
__device__ float g_cost[512];
__device__ float g_term[512];

// ---------------------------------------------------------------------------
// One block per batch. Everything row-wise lives in REGISTERS; SMEM holds only
// the reduced interface system, chunk-edge halos, and staged time/noise data.
// Solve: register Thomas on 8-row chunks + single-sync PCR on 256 interfaces.
// ---------------------------------------------------------------------------
__global__ void __launch_bounds__(P, 1)
fp_main(const float* __restrict__ mesh_time,
        const float* __restrict__ mesh_space,
        const float* __restrict__ init,
        const float* __restrict__ bw,
        float* __restrict__ out_density,
        int T, int N, int B)
{
    extern __shared__ float sm[];
    const int b    = blockIdx.x;
    const int tid  = threadIdx.x;
    const int lane = tid & 31;
    const int warp = tid >> 5;
    const int s0   = tid * M;

    // shared layout
    float* RA0 = sm;                 // reduced system, double-buffered [8*P]
    float* RB0 = RA0 + P;  float* RC0 = RB0 + P;  float* RD0 = RC0 + P;
    float* RA1 = RD0 + P;  float* RB1 = RA1 + P;  float* RC1 = RB1 + P;  float* RD1 = RC1 + P;
    float* ephi = RD1 + P;           // [P+1] interface exchange
    float* ealp = ephi + (P + 1);    // [P+1]
    float* egam = ealp + (P + 1);    // [P+1]
    float* sol  = egam + (P + 1);    // [P]
    float* tlo  = sol  + P;          // [P+1] stencil edges
    float* thi  = tlo  + (P + 1);    // [P]
    float* xlo  = thi  + P;          // [P+1] density edges
    float* xhi  = xlo  + (P + 1);    // [P]
    float* smt  = xhi  + P;          // [T]   mesh_time staged
    float* sbw  = smt  + T;          // [T-1] brownian row staged

    __shared__ float red[3 * NW];
    __shared__ float bcast[3];

    // ---- setup: geometry -> per-row affine constants, all in registers ----
    const float Kx = C_MEANREV - 0.5f;
    float xiv[M], wv[M], fsv[M], bsv[M];
    float a0v[M], a1v[M], b0v[M], b1v[M], c0v[M], c1v[M];
    float dnv[M];

    #pragma unroll
    for (int j = 0; j < M; ++j) {
        const int i = s0 + j;
        float xm = mesh_space[i];
        float xc = mesh_space[i + 1];
        float xp = mesh_space[i + 2];
        xiv[j] = xc;
        wv[j]  = (xp - xm) * 0.5f;
        float dxf = xp - xc;
        float dxb = xc - xm;
        float ctl = xp - xm;
        float fsj = 1.0f / (2.0f * dxf);
        float bsj = 1.0f / (2.0f * dxb);
        float ufj = 1.0f / (ctl * dxf);
        float ubj = 1.0f / (ctl * dxb);
        fsv[j] = fsj;  bsv[j] = bsj;
        // a = dt*(a0 + K1*a1), c = dt*(c0 + K1*c1), b = 1 + dt*(b0 + K1*b1)
        c1v[j] = -fsj;
        c0v[j] = -fsj * Kx * xp - C_DIFF * ufj;
        a1v[j] =  bsj;
        a0v[j] =  bsj * Kx * xm - C_DIFF * ubj;
        float bf = bsj - fsj;
        b1v[j] = -bf;
        b0v[j] = fmaxf(-xc, 0.0f) - bf * Kx * xc + C_DIFF * (ufj + ubj);
        dnv[j] = init[i];
    }
    if (tid == 0)     { a0v[0] = 0.f;     a1v[0] = 0.f; }
    if (tid == P - 1) { c0v[M - 1] = 0.f; c1v[M - 1] = 0.f; }

    // t = 0 trajectory slice
    {
        float4 v0, v1;
        v0.x = dnv[0]; v0.y = dnv[1]; v0.z = dnv[2]; v0.w = dnv[3];
        v1.x = dnv[4]; v1.y = dnv[5]; v1.z = dnv[6]; v1.w = dnv[7];
        float4* g4 = (float4*)(out_density + (size_t)b * T * N + s0);
        g4[0] = v0; g4[1] = v1;
    }

    // stage mesh_time + brownian row; density edges; pads
    for (int i = tid; i < T; i += P)     smt[i] = mesh_time[i];
    for (int i = tid; i < T - 1; i += P) sbw[i] = bw[(size_t)b * (T - 1) + i];
    xlo[tid] = dnv[0];  xhi[tid] = dnv[7];
    if (tid == 0) {
        xlo[P] = 0.f; tlo[P] = 0.f;
        ephi[P] = 0.f; ealp[P] = 0.f; egam[P] = 0.f;
    }

    // initial reductions for density0
    {
        float s_mean = 0.f, s_fb = 0.f, s_cost = 0.f;
        #pragma unroll
        for (int j = 0; j < M; ++j) {
            float dwv = dnv[j] * wv[j];
            float x   = xiv[j];
            s_mean += x * dwv;
            s_fb   += fmaxf(-x, 0.0f) * dwv;
            s_cost += 0.125f * x * x * dwv;
        }
        #pragma unroll
        for (int o = 16; o > 0; o >>= 1) {
            s_mean += __shfl_down_sync(0xffffffffu, s_mean, o);
            s_fb   += __shfl_down_sync(0xffffffffu, s_fb,   o);
            s_cost += __shfl_down_sync(0xffffffffu, s_cost, o);
        }
        if (lane == 0) { red[warp] = s_mean; red[NW + warp] = s_fb; red[2 * NW + warp] = s_cost; }
    }

    float costacc = 0.0f;   // meaningful on tid==0 only

    for (int st = 0; st < T - 1; ++st) {
        __syncthreads();                       // A: red + edge writes visible
        // ---- finalize block reduction of step-start density ----
        if (warp == 0) {
            float a = (lane < NW) ? red[lane]          : 0.0f;
            float f = (lane < NW) ? red[NW + lane]     : 0.0f;
            float c = (lane < NW) ? red[2 * NW + lane] : 0.0f;
            #pragma unroll
            for (int o = 4; o > 0; o >>= 1) {
                a += __shfl_down_sync(0xffffffffu, a, o);
                f += __shfl_down_sync(0xffffffffu, f, o);
                c += __shfl_down_sync(0xffffffffu, c, o);
            }
            if (lane == 0) { bcast[0] = a; bcast[1] = f; bcast[2] = c; }
        }
        __syncthreads();                       // B

        const float dt  = smt[st + 1] - smt[st];
        const float dW  = sbw[st];
        const float mean = bcast[0];
        const float fb   = bcast[1];           // FEEDBACK = 1
        if (tid == 0) costacc += dt * bcast[2];
        const float K1      = fb - C_MEANREV * mean;
        const float delta_t = C_VOL0 * C_VOL0 * (dW * dW - dt) * 0.5f;
        const float vdW     = C_VOL0 * dW;

        // ---- first-derivative stencil in registers (dens halo via edges) ----
        float d_m = (tid > 0) ? xhi[tid - 1] : 0.0f;
        float d_p = xlo[tid + 1];                     // xlo[P] = 0 pad
        float tpv[M];
        #pragma unroll
        for (int j = 0; j < M; ++j) {
            float dm = (j > 0)     ? dnv[j - 1] : d_m;
            float dp = (j < M - 1) ? dnv[j + 1] : d_p;
            tpv[j] = fsv[j] * (dp - dnv[j]) + bsv[j] * (dnv[j] - dm);
        }
        tlo[tid] = tpv[0];  thi[tid] = tpv[7];
        __syncthreads();                       // C
        const float tm_m = (tid > 0) ? thi[tid - 1] : 0.0f;
        const float tm_p = tlo[tid + 1];              // tlo[P] = 0 pad

        // ---- fused coefficient build + register Thomas (inline a,b,c,d) ----
        float Dw[M - 1], Aw[M - 1], Cw[M - 1];
        float a7, b7, c7, d7;
        {
            float gc = tpv[0], gp = tpv[1];
            float dj = dnv[0] - vdW * gc + delta_t * (fsv[0] * (gp - gc) + bsv[0] * (gc - tm_m));
            float aj = dt * fmaf(K1, a1v[0], a0v[0]);
            float bj = fmaf(dt, fmaf(K1, b1v[0], b0v[0]), 1.0f);
            float cj = dt * fmaf(K1, c1v[0], c0v[0]);
            float r = __frcp_rn(bj);
            Dw[0] = r * dj;  Aw[0] = r * aj;  Cw[0] = r * cj;
        }
        #pragma unroll
        for (int j = 1; j < M; ++j) {
            float gm = tpv[j - 1], gc = tpv[j];
            float gp = (j < M - 1) ? tpv[j + 1] : tm_p;
            float dj = dnv[j] - vdW * gc + delta_t * (fsv[j] * (gp - gc) + bsv[j] * (gc - gm));
            float aj = dt * fmaf(K1, a1v[j], a0v[j]);
            float bj = fmaf(dt, fmaf(K1, b1v[j], b0v[j]), 1.0f);
            float cj = dt * fmaf(K1, c1v[j], c0v[j]);
            if (j < M - 1) {
                float r = __frcp_rn(bj - aj * Cw[j - 1]);
                Dw[j] = r * (dj - aj * Dw[j - 1]);
                Aw[j] = -r * aj * Aw[j - 1];
                Cw[j] = r * cj;
            } else { a7 = aj; b7 = bj; c7 = cj; d7 = dj; }
        }
        #pragma unroll
        for (int j = M - 3; j >= 0; --j) {
            Dw[j] = Dw[j] - Cw[j] * Dw[j + 1];
            Aw[j] = Aw[j] - Cw[j] * Aw[j + 1];
            Cw[j] = -Cw[j] * Cw[j + 1];
        }

        ephi[tid] = Dw[0];  ealp[tid] = Aw[0];  egam[tid] = Cw[0];
        __syncthreads();                       // D

        // ---- reduced interface equation (row s0+M-1) ----
        {
            float pn = ephi[tid + 1], an = ealp[tid + 1], gn = egam[tid + 1];
            RA0[tid] = -a7 * Aw[M - 2];
            RB0[tid] =  b7 - a7 * Cw[M - 2] - c7 * an;
            RC0[tid] = -c7 * gn;
            RD0[tid] =  d7 - a7 * Dw[M - 2] - c7 * pn;
        }
        __syncthreads();                       // E

        // ---- PCR on reduced system: ONE sync per level ----
        float *Aa = RA0, *Bb = RB0, *Cc = RC0, *Dd = RD0;
        float *Ax = RA1, *Bx = RB1, *Cx = RC1, *Dx = RD1;
        for (int sh = 1; sh < P; sh <<= 1) {
            int im = tid - sh, ip = tid + sh;
            float aim, bim, cim, dim;
            if (im >= 0) { aim = Aa[im]; bim = Bb[im]; cim = Cc[im]; dim = Dd[im]; }
            else         { aim = 0.f; bim = 1.f; cim = 0.f; dim = 0.f; }
            float aip, bip, cip, dip;
            if (ip < P)  { aip = Aa[ip]; bip = Bb[ip]; cip = Cc[ip]; dip = Dd[ip]; }
            else         { aip = 0.f; bip = 1.f; cip = 0.f; dip = 0.f; }
            float al = -Aa[tid] * __frcp_rn(bim);
            float be = -Cc[tid] * __frcp_rn(bip);
            Ax[tid] = al * aim;
            Cx[tid] = be * cip;
            Bx[tid] = Bb[tid] + al * cim + be * aip;
            Dx[tid] = Dd[tid] + al * dim + be * dip;
            __syncthreads();                   // one barrier per level
            float* tp;
            tp = Aa; Aa = Ax; Ax = tp;
            tp = Bb; Bb = Bx; Bx = tp;
            tp = Cc; Cc = Cx; Cx = tp;
            tp = Dd; Dd = Dx; Dx = tp;
        }
        float Xt = Dd[tid] / Bb[tid];
        sol[tid] = Xt;
        __syncthreads();                       // F
        float Xm = (tid > 0) ? sol[tid - 1] : 0.0f;

        // ---- back-substitution, trajectory out, edges, fused reductions ----
        float xv[M];
        #pragma unroll
        for (int j = 0; j < M - 1; ++j)
            xv[j] = Dw[j] - Aw[j] * Xm - Cw[j] * Xt;
        xv[M - 1] = Xt;

        {
            float4 v0, v1;
            v0.x = xv[0]; v0.y = xv[1]; v0.z = xv[2]; v0.w = xv[3];
            v1.x = xv[4]; v1.y = xv[5]; v1.z = xv[6]; v1.w = xv[7];
            float4* g4 = (float4*)(out_density + (size_t)b * T * N + (size_t)(st + 1) * N + s0);
            g4[0] = v0; g4[1] = v1;
        }
        #pragma unroll
        for (int j = 0; j < M; ++j) dnv[j] = xv[j];
        xlo[tid] = xv[0];  xhi[tid] = xv[7];

        {
            float s_mean = 0.f, s_fb = 0.f, s_cost = 0.f;
            #pragma unroll
            for (int j = 0; j < M; ++j) {
                float dwv = xv[j] * wv[j];
                float x   = xiv[j];
                s_mean += x * dwv;
                s_fb   += fmaxf(-x, 0.0f) * dwv;
                s_cost += 0.125f * x * x * dwv;
            }
            #pragma unroll
            for (int o = 16; o > 0; o >>= 1) {
                s_mean += __shfl_down_sync(0xffffffffu, s_mean, o);
                s_fb   += __shfl_down_sync(0xffffffffu, s_fb,   o);
                s_cost += __shfl_down_sync(0xffffffffu, s_cost, o);
            }
            if (lane == 0) { red[warp] = s_mean; red[NW + warp] = s_fb; red[2 * NW + warp] = s_cost; }
        }
        // barrier A at top of next iteration separates these writes
    }

    // ---- terminal second moment + cost partials ----
    {
        float s_t = 0.f;
        #pragma unroll
        for (int j = 0; j < M; ++j) {
            float x = xiv[j];
            s_t += x * x * dnv[j] * wv[j];
        }
        #pragma unroll
        for (int o = 16; o > 0; o >>= 1) s_t += __shfl_down_sync(0xffffffffu, s_t, o);
        if (lane == 0) red[warp] = s_t;
    }
    __syncthreads();
    if (warp == 0) {
        float a = (lane < NW) ? red[lane] : 0.0f;
        #pragma unroll
        for (int o = 4; o > 0; o >>= 1) a += __shfl_down_sync(0xffffffffu, a, o);
        if (lane == 0) g_term[b] = a;
    }
    if (tid == 0) g_cost[b] = costacc;
}

// ---------------------------------------------------------------------------
// Deterministic finalize: average per-batch partials into the 2 cost slots.
// ---------------------------------------------------------------------------
__global__ void fp_finalize(float* __restrict__ out, int B, size_t off)
{
    __shared__ float rc[32], rt[32];
    int tid = threadIdx.x;
    float c = 0.0f, t = 0.0f;
    for (int i = tid; i < B; i += blockDim.x) { c += g_cost[i]; t += g_term[i]; }
    #pragma unroll
    for (int o = 16; o > 0; o >>= 1) {
        c += __shfl_down_sync(0xffffffffu, c, o);
        t += __shfl_down_sync(0xffffffffu, t, o);
    }
    int lane = tid & 31, warp = tid >> 5;
    if (lane == 0) { rc[warp] = c; rt[warp] = t; }
    __syncthreads();
    if (tid == 0) {
        float cs = 0.f, ts = 0.f;
        int nw = (blockDim.x + 31) >> 5;
        for (int wgt = 0; wgt < nw; ++wgt) { cs += rc[wgt]; ts += rt[wgt]; }
        out[off]     = cs / (float)B;
        out[off + 1] = ts / (float)B;
    }
}

extern "C" void kernel_launch(void* const* d_in, const int* in_sizes, int n_in,
                              void* d_out, int out_size)
{
    const float* mesh_time  = (const float*)d_in[0];
    const float* mesh_space = (const float*)d_in[1];
    const float* init       = (const float*)d_in[2];
    const float* bw         = (const float*)d_in[3];
    float* out = (float*)d_out;

    int T  = in_sizes[0];           // 129
    int Nx = in_sizes[1];           // 2050
    int N  = Nx - 2;                // 2048 (= P*M)
    int B  = in_sizes[3] / (T - 1); // 128

    // smem: reduced system + exchanges + edges + staged time/noise
    size_t smem = ((size_t)8 * P + 3 * (P + 1) + P
                   + (P + 1) + P + (P + 1) + P
                   + T + (T - 1)) * sizeof(float);   // ~17.5 KB

    fp_main<<<B, P, smem>>>(mesh_time, mesh_space, init, bw, out, T, N, B);
    fp_finalize<<<1, 128>>>(out, B, (size_t)B * T * N);
}

// round 10
// speedup vs baseline: 5.0253x; 1.0194x over previous
#include <cuda_runtime.h>
#include <math.h>

// Problem constants (from reference)
#define C_VOL0     0.2f
#define C_DIFF     0.13f              // VOL^2 + VOL0^2
#define C_MEANREV  0.1f

#define P  256          // threads per block
#define M  8            // rows per thread (N = P*M = 2048)
#define NW (P/32)       // warps per block (8 = number of PCR subsystems)

__device__ float g_cost[512];
__device__ float g_term[512];

__global__ void __launch_bounds__(P, 1)
fp_main(const float* __restrict__ mesh_time,
        const float* __restrict__ mesh_space,
        const float* __restrict__ init,
        const float* __restrict__ bw,
        float* __restrict__ out_density,
        int T, int N, int B)
{
    extern __shared__ float sm[];
    const int b    = blockIdx.x;
    const int tid  = threadIdx.x;
    const int lane = tid & 31;
    const int warp = tid >> 5;
    const int s0   = tid * M;
    const unsigned FULL = 0xffffffffu;

    // shared layout — xe (float4-accessed) FIRST after the 8P reduced-system
    // block so its float offset (8P) is 16-byte aligned.
    float* RA0 = sm;                 // reduced system, double-buffered [8*P]
    float* RB0 = RA0 + P;  float* RC0 = RB0 + P;  float* RD0 = RC0 + P;
    float* RA1 = RD0 + P;  float* RB1 = RA1 + P;  float* RC1 = RB1 + P;  float* RD1 = RC1 + P;
    float* xe   = RD1 + P;           // [4*P] density edges {d0,d1,d6,d7} per thread (16B aligned)
    float* ephi = xe + 4 * P;        // [P+1] interface exchange (pad at P)
    float* ealp = ephi + (P + 1);
    float* egam = ealp + (P + 1);
    float* sol  = egam + (P + 1);    // [P]
    float* smt  = sol  + P;          // [T]
    float* sbw  = smt  + T;          // [T-1]

    __shared__ float red[3 * NW];

    // ---- setup: geometry -> per-row affine constants, all in registers ----
    const float Kx = C_MEANREV - 0.5f;
    float xiv[M], wv[M], fsv[M], bsv[M];
    float a0v[M], a1v[M], b0v[M], b1v[M], c0v[M], c1v[M];
    float dnv[M];

    #pragma unroll
    for (int j = 0; j < M; ++j) {
        const int i = s0 + j;
        float xm = mesh_space[i];
        float xc = mesh_space[i + 1];
        float xp = mesh_space[i + 2];
        xiv[j] = xc;
        wv[j]  = (xp - xm) * 0.5f;
        float dxf = xp - xc;
        float dxb = xc - xm;
        float ctl = xp - xm;
        float fsj = 1.0f / (2.0f * dxf);
        float bsj = 1.0f / (2.0f * dxb);
        float ufj = 1.0f / (ctl * dxf);
        float ubj = 1.0f / (ctl * dxb);
        fsv[j] = fsj;  bsv[j] = bsj;
        c1v[j] = -fsj;
        c0v[j] = -fsj * Kx * xp - C_DIFF * ufj;
        a1v[j] =  bsj;
        a0v[j] =  bsj * Kx * xm - C_DIFF * ubj;
        float bf = bsj - fsj;
        b1v[j] = -bf;
        b0v[j] = fmaxf(-xc, 0.0f) - bf * Kx * xc + C_DIFF * (ufj + ubj);
        dnv[j] = init[i];
    }
    if (tid == 0)     { a0v[0] = 0.f;     a1v[0] = 0.f; }
    if (tid == P - 1) { c0v[M - 1] = 0.f; c1v[M - 1] = 0.f; }

    // neighbor-row geometry for halo stencil recompute (time-invariant)
    float fs_m1 = 0.f, bs_m1 = 0.f, fs_p1 = 0.f, bs_p1 = 0.f;
    if (tid > 0) {
        float xm = mesh_space[s0 - 1], xc = mesh_space[s0], xp = mesh_space[s0 + 1];
        fs_m1 = 1.0f / (2.0f * (xp - xc));
        bs_m1 = 1.0f / (2.0f * (xc - xm));
    }
    if (tid < P - 1) {
        float xm = mesh_space[s0 + M], xc = mesh_space[s0 + M + 1], xp = mesh_space[s0 + M + 2];
        fs_p1 = 1.0f / (2.0f * (xp - xc));
        bs_p1 = 1.0f / (2.0f * (xc - xm));
    }

    // t = 0 trajectory slice
    {
        float4 v0, v1;
        v0.x = dnv[0]; v0.y = dnv[1]; v0.z = dnv[2]; v0.w = dnv[3];
        v1.x = dnv[4]; v1.y = dnv[5]; v1.z = dnv[6]; v1.w = dnv[7];
        float4* g4 = (float4*)(out_density + (size_t)b * T * N + s0);
        g4[0] = v0; g4[1] = v1;
    }

    // stage mesh_time + brownian row; edges; pads
    for (int i = tid; i < T; i += P)     smt[i] = mesh_time[i];
    for (int i = tid; i < T - 1; i += P) sbw[i] = bw[(size_t)b * (T - 1) + i];
    {
        float4* x4 = (float4*)(xe + 4 * tid);
        float4 v; v.x = dnv[0]; v.y = dnv[1]; v.z = dnv[6]; v.w = dnv[7];
        *x4 = v;
    }
    if (tid == 0) { ephi[P] = 0.f; ealp[P] = 0.f; egam[P] = 0.f; }

    // initial per-warp reduction partials for density0
    {
        float s_mean = 0.f, s_fb = 0.f, s_cost = 0.f;
        #pragma unroll
        for (int j = 0; j < M; ++j) {
            float dwv = dnv[j] * wv[j];
            float x   = xiv[j];
            s_mean += x * dwv;
            s_fb   += fmaxf(-x, 0.0f) * dwv;
            s_cost += 0.125f * x * x * dwv;
        }
        #pragma unroll
        for (int o = 16; o > 0; o >>= 1) {
            s_mean += __shfl_down_sync(FULL, s_mean, o);
            s_fb   += __shfl_down_sync(FULL, s_fb,   o);
            s_cost += __shfl_down_sync(FULL, s_cost, o);
        }
        if (lane == 0) { red[warp] = s_mean; red[NW + warp] = s_fb; red[2 * NW + warp] = s_cost; }
    }

    float costacc = 0.0f;   // meaningful on tid==0 only

    for (int st = 0; st < T - 1; ++st) {
        __syncthreads();                       // A: red + xe writes visible

        // ---- block reduction: every thread sums the 8 warp partials ----
        float mean = 0.f, fb = 0.f, cst = 0.f;
        #pragma unroll
        for (int wq = 0; wq < NW; ++wq) {
            mean += red[wq];
            fb   += red[NW + wq];
            cst  += red[2 * NW + wq];
        }
        const float dt  = smt[st + 1] - smt[st];
        const float dW  = sbw[st];
        if (tid == 0) costacc += dt * cst;
        const float K1      = fb - C_MEANREV * mean;   // FEEDBACK = 1
        const float delta_t = C_VOL0 * C_VOL0 * (dW * dW - dt) * 0.5f;
        const float vdW     = C_VOL0 * dW;

        // ---- neighbor density edges (2-deep) ----
        float4 em, ep;
        if (tid > 0)     em = *(const float4*)(xe + 4 * (tid - 1));
        else             { em.x = em.y = em.z = em.w = 0.f; }
        if (tid < P - 1) ep = *(const float4*)(xe + 4 * (tid + 1));
        else             { ep.x = ep.y = ep.z = ep.w = 0.f; }
        const float d_m = em.w;     // dens[s0-1]
        const float d_p = ep.x;     // dens[s0+M]

        // ---- first-derivative stencil in registers ----
        float tpv[M];
        #pragma unroll
        for (int j = 0; j < M; ++j) {
            float dm = (j > 0)     ? dnv[j - 1] : d_m;
            float dp = (j < M - 1) ? dnv[j + 1] : d_p;
            tpv[j] = fsv[j] * (dp - dnv[j]) + bsv[j] * (dnv[j] - dm);
        }
        // halo stencil values recomputed locally (fs_m1=0 at tid 0 etc.)
        const float tm_m = fs_m1 * (dnv[0] - em.w) + bs_m1 * (em.w - em.z);
        const float tm_p = fs_p1 * (ep.y - ep.x) + bs_p1 * (ep.x - dnv[7]);

        // ---- fused coefficient build + register Thomas ----
        float Dw[M - 1], Aw[M - 1], Cw[M - 1];
        float a7, b7, c7, d7;
        {
            float gc = tpv[0], gp = tpv[1];
            float dj = dnv[0] - vdW * gc + delta_t * (fsv[0] * (gp - gc) + bsv[0] * (gc - tm_m));
            float aj = dt * fmaf(K1, a1v[0], a0v[0]);
            float bj = fmaf(dt, fmaf(K1, b1v[0], b0v[0]), 1.0f);
            float cj = dt * fmaf(K1, c1v[0], c0v[0]);
            float r = __frcp_rn(bj);
            Dw[0] = r * dj;  Aw[0] = r * aj;  Cw[0] = r * cj;
        }
        #pragma unroll
        for (int j = 1; j < M; ++j) {
            float gm = tpv[j - 1], gc = tpv[j];
            float gp = (j < M - 1) ? tpv[j + 1] : tm_p;
            float dj = dnv[j] - vdW * gc + delta_t * (fsv[j] * (gp - gc) + bsv[j] * (gc - gm));
            float aj = dt * fmaf(K1, a1v[j], a0v[j]);
            float bj = fmaf(dt, fmaf(K1, b1v[j], b0v[j]), 1.0f);
            float cj = dt * fmaf(K1, c1v[j], c0v[j]);
            if (j < M - 1) {
                float r = __frcp_rn(bj - aj * Cw[j - 1]);
                Dw[j] = r * (dj - aj * Dw[j - 1]);
                Aw[j] = -r * aj * Aw[j - 1];
                Cw[j] = r * cj;
            } else { a7 = aj; b7 = bj; c7 = cj; d7 = dj; }
        }
        #pragma unroll
        for (int j = M - 3; j >= 0; --j) {
            Dw[j] = Dw[j] - Cw[j] * Dw[j + 1];
            Aw[j] = Aw[j] - Cw[j] * Aw[j + 1];
            Cw[j] = -Cw[j] * Cw[j + 1];
        }

        ephi[tid] = Dw[0];  ealp[tid] = Aw[0];  egam[tid] = Cw[0];
        __syncthreads();                       // D

        // ---- reduced interface equation (row s0+M-1) ----
        {
            float pn = ephi[tid + 1], an = ealp[tid + 1], gn = egam[tid + 1];
            RA0[tid] = -a7 * Aw[M - 2];
            RB0[tid] =  b7 - a7 * Cw[M - 2] - c7 * an;
            RC0[tid] = -c7 * gn;
            RD0[tid] =  d7 - a7 * Dw[M - 2] - c7 * pn;
        }
        __syncthreads();                       // E

        // ---- 3 SMEM PCR levels: s = 1, 2, 4 ----
        #pragma unroll
        for (int lv = 0; lv < 3; ++lv) {
            const int sh = 1 << lv;
            const float *Aa, *Bb, *Cc, *Dd;
            float *Ax, *Bx, *Cx, *Dx;
            if (lv & 1) { Aa = RA1; Bb = RB1; Cc = RC1; Dd = RD1; Ax = RA0; Bx = RB0; Cx = RC0; Dx = RD0; }
            else        { Aa = RA0; Bb = RB0; Cc = RC0; Dd = RD0; Ax = RA1; Bx = RB1; Cx = RC1; Dx = RD1; }
            int im = tid - sh, ip = tid + sh;
            float aim, bim, cim, dim;
            if (im >= 0) { aim = Aa[im]; bim = Bb[im]; cim = Cc[im]; dim = Dd[im]; }
            else         { aim = 0.f; bim = 1.f; cim = 0.f; dim = 0.f; }
            float aip, bip, cip, dip;
            if (ip < P)  { aip = Aa[ip]; bip = Bb[ip]; cip = Cc[ip]; dip = Dd[ip]; }
            else         { aip = 0.f; bip = 1.f; cip = 0.f; dip = 0.f; }
            float al = -Aa[tid] * __frcp_rn(bim);
            float be = -Cc[tid] * __frcp_rn(bip);
            Ax[tid] = al * aim;
            Cx[tid] = be * cip;
            Bx[tid] = Bb[tid] + al * cim + be * aip;
            Dx[tid] = Dd[tid] + al * dim + be * dip;
            __syncthreads();                   // P1 / P2 / P3
        }

        // ---- gather stride-8 subsystem into warp, 5 shuffle PCR levels ----
        // after 3 levels (odd count) current data is in the RA1 set
        float ga, gb, gc, gd;
        {
            int row = warp + 8 * lane;         // subsystem = warp id
            ga = RA1[row]; gb = RB1[row]; gc = RC1[row]; gd = RD1[row];
        }
        #pragma unroll
        for (int k = 1; k <= 16; k <<= 1) {
            float am = __shfl_up_sync(FULL, ga, k);
            float bm = __shfl_up_sync(FULL, gb, k);
            float cm = __shfl_up_sync(FULL, gc, k);
            float dm = __shfl_up_sync(FULL, gd, k);
            if (lane < k) { am = 0.f; bm = 1.f; cm = 0.f; dm = 0.f; }
            float ap = __shfl_down_sync(FULL, ga, k);
            float bp = __shfl_down_sync(FULL, gb, k);
            float cp = __shfl_down_sync(FULL, gc, k);
            float dp = __shfl_down_sync(FULL, gd, k);
            if (lane >= 32 - k) { ap = 0.f; bp = 1.f; cp = 0.f; dp = 0.f; }
            float al = -ga * __frcp_rn(bm);
            float be = -gc * __frcp_rn(bp);
            ga = al * am;
            gc = be * cp;
            gb = gb + al * cm + be * ap;
            gd = gd + al * dm + be * dp;
        }
        sol[warp + 8 * lane] = gd / gb;
        __syncthreads();                       // F

        const float Xt = sol[tid];
        const float Xm = (tid > 0) ? sol[tid - 1] : 0.0f;

        // ---- back-substitution, trajectory out, edges, fused reductions ----
        float xv[M];
        #pragma unroll
        for (int j = 0; j < M - 1; ++j)
            xv[j] = Dw[j] - Aw[j] * Xm - Cw[j] * Xt;
        xv[M - 1] = Xt;

        {
            float4 v0, v1;
            v0.x = xv[0]; v0.y = xv[1]; v0.z = xv[2]; v0.w = xv[3];
            v1.x = xv[4]; v1.y = xv[5]; v1.z = xv[6]; v1.w = xv[7];
            float4* g4 = (float4*)(out_density + (size_t)b * T * N + (size_t)(st + 1) * N + s0);
            g4[0] = v0; g4[1] = v1;
        }
        #pragma unroll
        for (int j = 0; j < M; ++j) dnv[j] = xv[j];
        {
            float4* x4 = (float4*)(xe + 4 * tid);
            float4 v; v.x = xv[0]; v.y = xv[1]; v.z = xv[6]; v.w = xv[7];
            *x4 = v;
        }
        {
            float s_mean = 0.f, s_fb = 0.f, s_cost = 0.f;
            #pragma unroll
            for (int j = 0; j < M; ++j) {
                float dwv = xv[j] * wv[j];
                float x   = xiv[j];
                s_mean += x * dwv;
                s_fb   += fmaxf(-x, 0.0f) * dwv;
                s_cost += 0.125f * x * x * dwv;
            }
            #pragma unroll
            for (int o = 16; o > 0; o >>= 1) {
                s_mean += __shfl_down_sync(FULL, s_mean, o);
                s_fb   += __shfl_down_sync(FULL, s_fb,   o);
                s_cost += __shfl_down_sync(FULL, s_cost, o);
            }
            if (lane == 0) { red[warp] = s_mean; red[NW + warp] = s_fb; red[2 * NW + warp] = s_cost; }
        }
        // barrier A at top of next iteration orders these writes
    }

    // ---- terminal second moment + cost partials ----
    {
        float s_t = 0.f;
        #pragma unroll
        for (int j = 0; j < M; ++j) {
            float x = xiv[j];
            s_t += x * x * dnv[j] * wv[j];
        }
        #pragma unroll
        for (int o = 16; o > 0; o >>= 1) s_t += __shfl_down_sync(FULL, s_t, o);
        if (lane == 0) red[warp] = s_t;
    }
    __syncthreads();
    if (tid == 0) {
        float a = 0.f;
        for (int wq = 0; wq < NW; ++wq) a += red[wq];
        g_term[b] = a;
        g_cost[b] = costacc;
    }
}

__global__ void fp_finalize(float* __restrict__ out, int B, size_t off)
{
    __shared__ float rc[32], rt[32];
    int tid = threadIdx.x;
    float c = 0.0f, t = 0.0f;
    for (int i = tid; i < B; i += blockDim.x) { c += g_cost[i]; t += g_term[i]; }
    #pragma unroll
    for (int o = 16; o > 0; o >>= 1) {
        c += __shfl_down_sync(0xffffffffu, c, o);
        t += __shfl_down_sync(0xffffffffu, t, o);
    }
    int lane = tid & 31, warp = tid >> 5;
    if (lane == 0) { rc[warp] = c; rt[warp] = t; }
    __syncthreads();
    if (tid == 0) {
        float cs = 0.f, ts = 0.f;
        int nw = (blockDim.x + 31) >> 5;
        for (int wgt = 0; wgt < nw; ++wgt) { cs += rc[wgt]; ts += rt[wgt]; }
        out[off]     = cs / (float)B;
        out[off + 1] = ts / (float)B;
    }
}

extern "C" void kernel_launch(void* const* d_in, const int* in_sizes, int n_in,
                              void* d_out, int out_size)
{
    const float* mesh_time  = (const float*)d_in[0];
    const float* mesh_space = (const float*)d_in[1];
    const float* init       = (const float*)d_in[2];
    const float* bw         = (const float*)d_in[3];
    float* out = (float*)d_out;

    int T  = in_sizes[0];           // 129
    int Nx = in_sizes[1];           // 2050
    int N  = Nx - 2;                // 2048 (= P*M)
    int B  = in_sizes[3] / (T - 1); // 128

    size_t smem = ((size_t)8 * P + 4 * P + 3 * (P + 1) + P
                   + T + (T - 1)) * sizeof(float);   // ~17.5 KB

    fp_main<<<B, P, smem>>>(mesh_time, mesh_space, init, bw, out, T, N, B);
    fp_finalize<<<1, 128>>>(out, B, (size_t)B * T * N);
}